// round 1
// baseline (speedup 1.0000x reference)
#include <cuda_runtime.h>

#define T_TOK 8192
#define HDIM  2048
#define NEXP  8
#define BM 128
#define BN 128
#define BK 16

// Routing scratch (device globals: no allocations allowed)
__device__ int   d_cnt[NEXP];
__device__ int   d_list[NEXP * T_TOK];
__device__ float d_gatev[NEXP * T_TOK];

// ---------------------------------------------------------------------------
// Kernel 0: zero the output buffer (poisoned by harness) and expert counters.
// ---------------------------------------------------------------------------
__global__ void init_kernel(float* __restrict__ out) {
    int i = blockIdx.x * blockDim.x + threadIdx.x;
    if (i < NEXP) d_cnt[i] = 0;
    const int n4 = (T_TOK * HDIM) / 4;
    float4 z = make_float4(0.f, 0.f, 0.f, 0.f);
    float4* o4 = (float4*)out;
    for (int j = i; j < n4; j += gridDim.x * blockDim.x) o4[j] = z;
}

// ---------------------------------------------------------------------------
// Kernel 1: router. One thread per token: logits = x[t]·Wg + bg, softmax,
// top-2 selection, append (token, gate) to per-expert lists.
// Wg accesses are warp-uniform per h-step -> broadcast from L1.
// ---------------------------------------------------------------------------
__global__ void router_kernel(const float* __restrict__ x,
                              const float* __restrict__ Wg,
                              const float* __restrict__ bg) {
    int t = blockIdx.x * blockDim.x + threadIdx.x;
    if (t >= T_TOK) return;

    float acc[NEXP];
#pragma unroll
    for (int e = 0; e < NEXP; e++) acc[e] = bg[e];

    const float4* xr = (const float4*)(x + (size_t)t * HDIM);
#pragma unroll 4
    for (int h4 = 0; h4 < HDIM / 4; h4++) {
        float4 xv = xr[h4];
        int h = h4 * 4;
#pragma unroll
        for (int j = 0; j < 4; j++) {
            float xs = (j == 0) ? xv.x : (j == 1) ? xv.y : (j == 2) ? xv.z : xv.w;
            const float4* wr = (const float4*)(Wg + (size_t)(h + j) * NEXP);
            float4 w0 = wr[0];
            float4 w1 = wr[1];
            acc[0] += xs * w0.x; acc[1] += xs * w0.y;
            acc[2] += xs * w0.z; acc[3] += xs * w0.w;
            acc[4] += xs * w1.x; acc[5] += xs * w1.y;
            acc[6] += xs * w1.z; acc[7] += xs * w1.w;
        }
    }

    // softmax over 8 logits
    float m = acc[0];
#pragma unroll
    for (int e = 1; e < NEXP; e++) m = fmaxf(m, acc[e]);
    float p[NEXP];
    float s = 0.f;
#pragma unroll
    for (int e = 0; e < NEXP; e++) { p[e] = __expf(acc[e] - m); s += p[e]; }
    float inv = 1.f / s;
#pragma unroll
    for (int e = 0; e < NEXP; e++) p[e] *= inv;

    // top-2 (strict > : lowest index wins ties, matching jax top_k set)
    int i0 = 0;
#pragma unroll
    for (int e = 1; e < NEXP; e++) if (p[e] > p[i0]) i0 = e;
    int i1 = (i0 == 0) ? 1 : 0;
#pragma unroll
    for (int e = 0; e < NEXP; e++) if (e != i0 && p[e] > p[i1]) i1 = e;

    int pos0 = atomicAdd(&d_cnt[i0], 1);
    d_list[i0 * T_TOK + pos0]  = t;
    d_gatev[i0 * T_TOK + pos0] = p[i0];
    int pos1 = atomicAdd(&d_cnt[i1], 1);
    d_list[i1 * T_TOK + pos1]  = t;
    d_gatev[i1 * T_TOK + pos1] = p[i1];
}

// ---------------------------------------------------------------------------
// Kernel 2: grouped gathered SGEMM.
// grid = (HDIM/BN, T_TOK/BM, NEXP); blocks past an expert's token count exit.
// out[tok] += gate * (x[tok] @ We[e] + be[e])  via fp32 atomics
// (exactly 2 commutative adds per output element -> deterministic).
// ---------------------------------------------------------------------------
__global__ void __launch_bounds__(256, 2)
moe_gemm_kernel(const float* __restrict__ x,
                const float* __restrict__ We,
                const float* __restrict__ be,
                float* __restrict__ out) {
    const int e   = blockIdx.z;
    const int cnt = d_cnt[e];
    const int m0  = blockIdx.y * BM;
    if (m0 >= cnt) return;
    const int n0  = blockIdx.x * BN;

    __shared__ float As[BK][BM + 4];   // transposed A, padded vs bank conflicts
    __shared__ float Bs[BK][BN + 4];
    __shared__ int   sTok[BM];
    __shared__ float sGate[BM];

    const int tid = threadIdx.x;

    if (tid < BM) {
        int r = m0 + tid;
        if (r < cnt) {
            sTok[tid]  = d_list[e * T_TOK + r];
            sGate[tid] = d_gatev[e * T_TOK + r];
        } else {
            sTok[tid]  = 0;      // safe dummy row
            sGate[tid] = 0.f;
        }
    }
    __syncthreads();

    const float* Be = We + (size_t)e * HDIM * HDIM;

    const int tx = tid & 15;        // 0..15 -> n microtile
    const int ty = tid >> 4;        // 0..15 -> m microtile

    // A-load mapping: 2 threads per row, 8 k's each
    const int am = tid >> 1;
    const int kh = (tid & 1) * 8;
    const size_t a_row_base = (size_t)sTok[am] * HDIM + kh;

    // B-load mapping: 16 threads per k-row, 8 n's each
    const int kb = tid >> 4;
    const int cb = (tid & 15) * 8;

    float accv[8][8];
#pragma unroll
    for (int i = 0; i < 8; i++)
#pragma unroll
        for (int j = 0; j < 8; j++) accv[i][j] = 0.f;

    for (int k0 = 0; k0 < HDIM; k0 += BK) {
        // --- stage A (transposed) ---
        const float* xrow = x + a_row_base + k0;
        float4 a0 = *(const float4*)(xrow);
        float4 a1 = *(const float4*)(xrow + 4);
        As[kh + 0][am] = a0.x; As[kh + 1][am] = a0.y;
        As[kh + 2][am] = a0.z; As[kh + 3][am] = a0.w;
        As[kh + 4][am] = a1.x; As[kh + 5][am] = a1.y;
        As[kh + 6][am] = a1.z; As[kh + 7][am] = a1.w;

        // --- stage B ---
        const float* brow = Be + (size_t)(k0 + kb) * HDIM + n0 + cb;
        float4 b0 = *(const float4*)(brow);
        float4 b1 = *(const float4*)(brow + 4);
        *(float4*)&Bs[kb][cb]     = b0;
        *(float4*)&Bs[kb][cb + 4] = b1;

        __syncthreads();

#pragma unroll
        for (int k = 0; k < BK; k++) {
            float a[8], b[8];
            *(float4*)&a[0] = *(const float4*)&As[k][ty * 8];
            *(float4*)&a[4] = *(const float4*)&As[k][ty * 8 + 4];
            *(float4*)&b[0] = *(const float4*)&Bs[k][tx * 8];
            *(float4*)&b[4] = *(const float4*)&Bs[k][tx * 8 + 4];
#pragma unroll
            for (int i = 0; i < 8; i++)
#pragma unroll
                for (int j = 0; j < 8; j++)
                    accv[i][j] += a[i] * b[j];
        }
        __syncthreads();
    }

    // --- epilogue: out[tok] += gate * (acc + be[e]) ---
    float bee[8];
#pragma unroll
    for (int j = 0; j < 8; j++) bee[j] = be[e * HDIM + n0 + tx * 8 + j];

#pragma unroll
    for (int i = 0; i < 8; i++) {
        int r = ty * 8 + i;
        if (m0 + r < cnt) {
            int tok = sTok[r];
            float g = sGate[r];
            float* orow = out + (size_t)tok * HDIM + n0 + tx * 8;
#pragma unroll
            for (int j = 0; j < 8; j++) {
                atomicAdd(&orow[j], g * (accv[i][j] + bee[j]));
            }
        }
    }
}

// ---------------------------------------------------------------------------
extern "C" void kernel_launch(void* const* d_in, const int* in_sizes, int n_in,
                              void* d_out, int out_size) {
    const float* x  = (const float*)d_in[0];
    const float* Wg = (const float*)d_in[1];
    const float* bg = (const float*)d_in[2];
    const float* We = (const float*)d_in[3];
    const float* be = (const float*)d_in[4];
    float* out = (float*)d_out;

    init_kernel<<<512, 256>>>(out);
    router_kernel<<<(T_TOK + 255) / 256, 256>>>(x, Wg, bg);

    dim3 grid(HDIM / BN, T_TOK / BM, NEXP);
    moe_gemm_kernel<<<grid, 256>>>(x, We, be, out);
}

// round 3
// speedup vs baseline: 1.7926x; 1.7926x over previous
#include <cuda_runtime.h>
#include <cuda_bf16.h>
#include <cstdint>

#define T_TOK 8192
#define HDIM  2048
#define NEXP  8

// GEMM tile config (mma.sync path; tcgen05 not available under compute_103)
#define BM 128
#define BN 128
#define BKC 64                     // K per chunk = 128B bf16 rows (SW128)
#define NCHUNK (HDIM / BKC)        // 32
#define NSTAGE 3
// per-stage SMEM regions (bytes)
#define A_HI_OFF 0
#define A_LO_OFF 16384
#define B_HI_OFF 32768
#define B_LO_OFF 49152
#define STAGE_BYTES 65536
#define SM_HDR 1024
#define SMEM_TOTAL (SM_HDR + NSTAGE * STAGE_BYTES)   // 197632

// ---------------- device scratch (no allocations allowed) -------------------
__device__ int   d_cnt[NEXP];
__device__ int   d_list[NEXP * T_TOK];
__device__ float d_gatev[NEXP * T_TOK];
__device__ __nv_bfloat16 d_xhi[(size_t)T_TOK * HDIM];
__device__ __nv_bfloat16 d_xlo[(size_t)T_TOK * HDIM];
__device__ __nv_bfloat16 d_wthi[(size_t)NEXP * HDIM * HDIM];   // We^T [e][n][k]
__device__ __nv_bfloat16 d_wtlo[(size_t)NEXP * HDIM * HDIM];

// ---------------- helpers ---------------------------------------------------
__device__ __forceinline__ uint32_t smem_u32(const void* p) {
    uint32_t a;
    asm("{ .reg .u64 t; cvta.to.shared.u64 t, %1; cvt.u32.u64 %0, t; }" : "=r"(a) : "l"(p));
    return a;
}
__device__ __forceinline__ void cp16(uint32_t dst, const void* src) {
    asm volatile("cp.async.cg.shared.global [%0], [%1], 16;" :: "r"(dst), "l"(src));
}
__device__ __forceinline__ void ldm4(uint32_t addr, uint32_t& r0, uint32_t& r1,
                                     uint32_t& r2, uint32_t& r3) {
    asm volatile("ldmatrix.sync.aligned.m8n8.x4.shared.b16 {%0,%1,%2,%3}, [%4];"
                 : "=r"(r0), "=r"(r1), "=r"(r2), "=r"(r3) : "r"(addr));
}
__device__ __forceinline__ void mma16816(float* c, const uint32_t* a,
                                         uint32_t b0, uint32_t b1) {
    asm volatile(
        "mma.sync.aligned.m16n8k16.row.col.f32.bf16.bf16.f32 "
        "{%0,%1,%2,%3}, {%4,%5,%6,%7}, {%8,%9}, {%0,%1,%2,%3};"
        : "+f"(c[0]), "+f"(c[1]), "+f"(c[2]), "+f"(c[3])
        : "r"(a[0]), "r"(a[1]), "r"(a[2]), "r"(a[3]), "r"(b0), "r"(b1));
}

// ---------------- kernel 0: init --------------------------------------------
__global__ void init_kernel(float* __restrict__ out) {
    int i = blockIdx.x * blockDim.x + threadIdx.x;
    if (i < NEXP) d_cnt[i] = 0;
    const int n4 = (T_TOK * HDIM) / 4;
    float4 z = make_float4(0.f, 0.f, 0.f, 0.f);
    float4* o4 = (float4*)out;
    for (int j = i; j < n4; j += gridDim.x * blockDim.x) o4[j] = z;
}

// ---------------- kernel 1: split x into bf16 hi/lo --------------------------
__global__ void convert_x(const float* __restrict__ x) {
    int n = (T_TOK * HDIM) / 4;
    const float4* x4 = (const float4*)x;
    for (int i = blockIdx.x * blockDim.x + threadIdx.x; i < n; i += gridDim.x * blockDim.x) {
        float4 v = x4[i];
        __nv_bfloat16 h0 = __float2bfloat16_rn(v.x), h1 = __float2bfloat16_rn(v.y);
        __nv_bfloat16 h2 = __float2bfloat16_rn(v.z), h3 = __float2bfloat16_rn(v.w);
        __nv_bfloat16 l0 = __float2bfloat16_rn(v.x - __bfloat162float(h0));
        __nv_bfloat16 l1 = __float2bfloat16_rn(v.y - __bfloat162float(h1));
        __nv_bfloat16 l2 = __float2bfloat16_rn(v.z - __bfloat162float(h2));
        __nv_bfloat16 l3 = __float2bfloat16_rn(v.w - __bfloat162float(h3));
        __nv_bfloat162 hv0 = {h0, h1}, hv1 = {h2, h3}, lv0 = {l0, l1}, lv1 = {l2, l3};
        ((__nv_bfloat162*)d_xhi)[2 * i]     = hv0;
        ((__nv_bfloat162*)d_xhi)[2 * i + 1] = hv1;
        ((__nv_bfloat162*)d_xlo)[2 * i]     = lv0;
        ((__nv_bfloat162*)d_xlo)[2 * i + 1] = lv1;
    }
}

// ---------------- kernel 2: transpose + split We -----------------------------
__global__ void transpose_we(const float* __restrict__ We) {
    __shared__ float tile[32][33];
    int e = blockIdx.z;
    int n0 = blockIdx.x * 32, k0 = blockIdx.y * 32;
    int tx = threadIdx.x & 31, ty = threadIdx.x >> 5;   // 32 x 8
    const float* src = We + ((size_t)e * HDIM + k0) * HDIM + n0;
#pragma unroll
    for (int i = 0; i < 4; i++)
        tile[ty + 8 * i][tx] = src[(size_t)(ty + 8 * i) * HDIM + tx];
    __syncthreads();
    size_t ob = ((size_t)e * HDIM + n0) * HDIM + k0;
#pragma unroll
    for (int i = 0; i < 4; i++) {
        float v = tile[tx][ty + 8 * i];
        __nv_bfloat16 h = __float2bfloat16_rn(v);
        __nv_bfloat16 l = __float2bfloat16_rn(v - __bfloat162float(h));
        d_wthi[ob + (size_t)(ty + 8 * i) * HDIM + tx] = h;
        d_wtlo[ob + (size_t)(ty + 8 * i) * HDIM + tx] = l;
    }
}

// ---------------- kernel 3: router -------------------------------------------
__global__ void router_kernel(const float* __restrict__ x,
                              const float* __restrict__ Wg,
                              const float* __restrict__ bg) {
    int t = blockIdx.x * blockDim.x + threadIdx.x;
    if (t >= T_TOK) return;
    float acc[NEXP];
#pragma unroll
    for (int e = 0; e < NEXP; e++) acc[e] = bg[e];
    const float4* xr = (const float4*)(x + (size_t)t * HDIM);
#pragma unroll 4
    for (int h4 = 0; h4 < HDIM / 4; h4++) {
        float4 xv = xr[h4];
        int h = h4 * 4;
#pragma unroll
        for (int j = 0; j < 4; j++) {
            float xs = (j == 0) ? xv.x : (j == 1) ? xv.y : (j == 2) ? xv.z : xv.w;
            const float4* wr = (const float4*)(Wg + (size_t)(h + j) * NEXP);
            float4 w0 = wr[0], w1 = wr[1];
            acc[0] += xs * w0.x; acc[1] += xs * w0.y;
            acc[2] += xs * w0.z; acc[3] += xs * w0.w;
            acc[4] += xs * w1.x; acc[5] += xs * w1.y;
            acc[6] += xs * w1.z; acc[7] += xs * w1.w;
        }
    }
    float m = acc[0];
#pragma unroll
    for (int e = 1; e < NEXP; e++) m = fmaxf(m, acc[e]);
    float p[NEXP], s = 0.f;
#pragma unroll
    for (int e = 0; e < NEXP; e++) { p[e] = __expf(acc[e] - m); s += p[e]; }
    float inv = 1.f / s;
#pragma unroll
    for (int e = 0; e < NEXP; e++) p[e] *= inv;
    int i0 = 0;
#pragma unroll
    for (int e = 1; e < NEXP; e++) if (p[e] > p[i0]) i0 = e;
    int i1 = (i0 == 0) ? 1 : 0;
#pragma unroll
    for (int e = 0; e < NEXP; e++) if (e != i0 && p[e] > p[i1]) i1 = e;
    int pos0 = atomicAdd(&d_cnt[i0], 1);
    d_list[i0 * T_TOK + pos0] = t;  d_gatev[i0 * T_TOK + pos0] = p[i0];
    int pos1 = atomicAdd(&d_cnt[i1], 1);
    d_list[i1 * T_TOK + pos1] = t;  d_gatev[i1 * T_TOK + pos1] = p[i1];
}

// ---------------- kernel 4: grouped GEMM via mma.sync bf16 -------------------
__global__ void __launch_bounds__(256, 1)
moe_gemm_mma(const float* __restrict__ be, float* __restrict__ out) {
    const int e = blockIdx.z;
    const int cnt = d_cnt[e];
    const int m0 = blockIdx.y * BM;
    if (m0 >= cnt) return;
    const int n0 = blockIdx.x * BN;

    extern __shared__ char smem[];
    const uint32_t sb = smem_u32(smem);
    const int tid  = threadIdx.x;
    const int wid  = tid >> 5;
    const int lane = tid & 31;
    const int wm   = wid >> 2;       // 0..1  (m: 64 each)
    const int wn   = wid & 3;        // 0..3  (n: 32 each)

    int*   sTok  = (int*)smem;
    float* sGate = (float*)(smem + 512);

    if (tid < BM) {
        int r = m0 + tid;
        if (r < cnt) { sTok[tid] = d_list[e * T_TOK + r]; sGate[tid] = d_gatev[e * T_TOK + r]; }
        else         { sTok[tid] = 0;                      sGate[tid] = 0.f; }
    }
    __syncthreads();

    // --- gmem gather sources (per thread; constant across chunks) ---
    const int row2 = tid >> 1;           // 0..127
    const int half = tid & 1;            // 64B half of the 128B row
    uint32_t sD[4];
#pragma unroll
    for (int i = 0; i < 4; i++) {
        uint32_t o = row2 * 128 + (half * 4 + i) * 16;
        sD[i] = o ^ ((o >> 3) & 0x70);   // SW128
    }
    const __nv_bfloat16* aHiS = d_xhi + (size_t)sTok[row2] * HDIM + half * 32;
    const __nv_bfloat16* aLoS = d_xlo + (size_t)sTok[row2] * HDIM + half * 32;
    const __nv_bfloat16* bHiS = d_wthi + ((size_t)e * HDIM + n0 + row2) * HDIM + half * 32;
    const __nv_bfloat16* bLoS = d_wtlo + ((size_t)e * HDIM + n0 + row2) * HDIM + half * 32;

#define ISSUE_CHUNK(stage, k0)                                            \
    {                                                                     \
        _Pragma("unroll")                                                 \
        for (int i = 0; i < 4; i++) {                                     \
            cp16((stage) + A_HI_OFF + sD[i], aHiS + (k0) + i * 8);        \
            cp16((stage) + A_LO_OFF + sD[i], aLoS + (k0) + i * 8);        \
            cp16((stage) + B_HI_OFF + sD[i], bHiS + (k0) + i * 8);        \
            cp16((stage) + B_LO_OFF + sD[i], bLoS + (k0) + i * 8);        \
        }                                                                 \
        asm volatile("cp.async.commit_group;" ::: "memory");              \
    }

    // --- ldmatrix addressing (per lane; row base + per-kstep xor chunk) ---
    // A frag mi: rows wm*64 + mi*16 + (lane&15); B frag-pair j: rows wn*32 + j*16 + (lane&15)
    uint32_t aRow[4], bRow[2];
#pragma unroll
    for (int mi = 0; mi < 4; mi++) aRow[mi] = wm * 64 + mi * 16 + (lane & 15);
#pragma unroll
    for (int j = 0; j < 2; j++)    bRow[j]  = wn * 32 + j * 16 + (lane & 15);
    const uint32_t kcHalf = (lane >> 4);   // 0 or 1: which 16B chunk of the k16

    float acc[4][4][4];
#pragma unroll
    for (int mi = 0; mi < 4; mi++)
#pragma unroll
        for (int nj = 0; nj < 4; nj++)
#pragma unroll
            for (int q = 0; q < 4; q++) acc[mi][nj][q] = 0.f;

    const uint32_t stgBase = sb + SM_HDR;

    // prologue: fill 3 stages
    ISSUE_CHUNK(stgBase + 0 * STAGE_BYTES, 0);
    ISSUE_CHUNK(stgBase + 1 * STAGE_BYTES, BKC);
    ISSUE_CHUNK(stgBase + 2 * STAGE_BYTES, 2 * BKC);

    int sidx = 0;
    for (int c = 0; c < NCHUNK; c++) {
        asm volatile("cp.async.wait_group 2;" ::: "memory");
        __syncthreads();
        const uint32_t stage = stgBase + sidx * STAGE_BYTES;

#pragma unroll
        for (int ks = 0; ks < 4; ks++) {
            const uint32_t kc = ks * 2 + kcHalf;
            uint32_t ah[4][4], al[4][4];
#pragma unroll
            for (int mi = 0; mi < 4; mi++) {
                uint32_t off = aRow[mi] * 128 + ((kc ^ (aRow[mi] & 7)) << 4);
                ldm4(stage + A_HI_OFF + off, ah[mi][0], ah[mi][1], ah[mi][2], ah[mi][3]);
                ldm4(stage + A_LO_OFF + off, al[mi][0], al[mi][1], al[mi][2], al[mi][3]);
            }
            uint32_t bh[2][4], bl[2][4];
#pragma unroll
            for (int j = 0; j < 2; j++) {
                uint32_t off = bRow[j] * 128 + ((kc ^ (bRow[j] & 7)) << 4);
                ldm4(stage + B_HI_OFF + off, bh[j][0], bh[j][1], bh[j][2], bh[j][3]);
                ldm4(stage + B_LO_OFF + off, bl[j][0], bl[j][1], bl[j][2], bl[j][3]);
            }
            // b frag for nj: j = nj>>1, hi-half = nj&1 : regs {r[hi], r[hi+... ]}
            // regs layout from ldm4 on [n][k]: r0=(n_lo,k0) r1=(n_hi,k0) r2=(n_lo,k8) r3=(n_hi,k8)
#pragma unroll
            for (int mi = 0; mi < 4; mi++) {
#pragma unroll
                for (int nj = 0; nj < 4; nj++) {
                    const int j = nj >> 1, h = nj & 1;
                    mma16816(acc[mi][nj], ah[mi], bh[j][h], bh[j][h + 2]);  // hi*hi
                    mma16816(acc[mi][nj], ah[mi], bl[j][h], bl[j][h + 2]);  // hi*lo
                    mma16816(acc[mi][nj], al[mi], bh[j][h], bh[j][h + 2]);  // lo*hi
                }
            }
        }

        __syncthreads();
        if (c + NSTAGE < NCHUNK) {
            ISSUE_CHUNK(stage, (c + NSTAGE) * BKC);
        } else {
            asm volatile("cp.async.commit_group;" ::: "memory");
        }
        sidx = (sidx == NSTAGE - 1) ? 0 : sidx + 1;
    }

    // --- epilogue: out[tok] += gate * (acc + be[e]) ---
    const float* beg = be + (size_t)e * HDIM + n0;
    const int cl = (lane & 3) * 2;
    const int rl = lane >> 2;
#pragma unroll
    for (int mi = 0; mi < 4; mi++) {
        const int r0 = wm * 64 + mi * 16 + rl;
        const int r1 = r0 + 8;
        const bool v0 = (m0 + r0) < cnt;
        const bool v1 = (m0 + r1) < cnt;
        const int   t0 = sTok[r0], t1 = sTok[r1];
        const float g0 = sGate[r0], g1 = sGate[r1];
        float* o0 = out + (size_t)t0 * HDIM + n0;
        float* o1 = out + (size_t)t1 * HDIM + n0;
#pragma unroll
        for (int nj = 0; nj < 4; nj++) {
            const int col = wn * 32 + nj * 8 + cl;
            const float b0 = beg[col], b1 = beg[col + 1];
            if (v0) {
                atomicAdd(&o0[col],     g0 * (acc[mi][nj][0] + b0));
                atomicAdd(&o0[col + 1], g0 * (acc[mi][nj][1] + b1));
            }
            if (v1) {
                atomicAdd(&o1[col],     g1 * (acc[mi][nj][2] + b0));
                atomicAdd(&o1[col + 1], g1 * (acc[mi][nj][3] + b1));
            }
        }
    }
}

// ---------------------------------------------------------------------------
extern "C" void kernel_launch(void* const* d_in, const int* in_sizes, int n_in,
                              void* d_out, int out_size) {
    const float* x  = (const float*)d_in[0];
    const float* Wg = (const float*)d_in[1];
    const float* bg = (const float*)d_in[2];
    const float* We = (const float*)d_in[3];
    const float* be = (const float*)d_in[4];
    float* out = (float*)d_out;

    cudaFuncSetAttribute(moe_gemm_mma, cudaFuncAttributeMaxDynamicSharedMemorySize, SMEM_TOTAL);

    init_kernel<<<512, 256>>>(out);
    convert_x<<<2048, 256>>>(x);
    dim3 tg(HDIM / 32, HDIM / 32, NEXP);
    transpose_we<<<tg, 256>>>(We);
    router_kernel<<<(T_TOK + 255) / 256, 256>>>(x, Wg, bg);

    dim3 grid(HDIM / BN, T_TOK / BM, NEXP);
    moe_gemm_mma<<<grid, 256, SMEM_TOTAL>>>(be, out);
}

// round 5
// speedup vs baseline: 1.9838x; 1.1067x over previous
#include <cuda_runtime.h>
#include <cuda_bf16.h>
#include <cstdint>

#define T_TOK 8192
#define HDIM  2048
#define NEXP  8

// GEMM tile config (mma.sync path; tcgen05 not available under compute_103)
#define BM 128
#define BN 128
#define BKC 64                     // K per chunk = 128B bf16 rows (SW128)
#define NCHUNK (HDIM / BKC)        // 32
#define NSTAGE 3
// per-stage SMEM regions (bytes)
#define A_HI_OFF 0
#define A_LO_OFF 16384
#define B_HI_OFF 32768
#define B_LO_OFF 49152
#define STAGE_BYTES 65536
#define SM_HDR 1024
#define SMEM_TOTAL (SM_HDR + NSTAGE * STAGE_BYTES)   // 197632

// ---------------- device scratch (no allocations allowed) -------------------
__device__ int   d_cnt[NEXP];
__device__ int   d_list[NEXP * T_TOK];
__device__ float d_gatev[NEXP * T_TOK];
__device__ __nv_bfloat16 d_xhi[(size_t)T_TOK * HDIM];
__device__ __nv_bfloat16 d_xlo[(size_t)T_TOK * HDIM];
__device__ __nv_bfloat16 d_wthi[(size_t)NEXP * HDIM * HDIM];   // We^T [e][n][k]
__device__ __nv_bfloat16 d_wtlo[(size_t)NEXP * HDIM * HDIM];

// ---------------- helpers ---------------------------------------------------
__device__ __forceinline__ uint32_t smem_u32(const void* p) {
    uint32_t a;
    asm("{ .reg .u64 t; cvta.to.shared.u64 t, %1; cvt.u32.u64 %0, t; }" : "=r"(a) : "l"(p));
    return a;
}
__device__ __forceinline__ void cp16(uint32_t dst, const void* src) {
    asm volatile("cp.async.cg.shared.global [%0], [%1], 16;" :: "r"(dst), "l"(src));
}
__device__ __forceinline__ void ldm4(uint32_t addr, uint32_t& r0, uint32_t& r1,
                                     uint32_t& r2, uint32_t& r3) {
    asm volatile("ldmatrix.sync.aligned.m8n8.x4.shared.b16 {%0,%1,%2,%3}, [%4];"
                 : "=r"(r0), "=r"(r1), "=r"(r2), "=r"(r3) : "r"(addr));
}
__device__ __forceinline__ void mma16816(float* c, const uint32_t* a,
                                         uint32_t b0, uint32_t b1) {
    asm volatile(
        "mma.sync.aligned.m16n8k16.row.col.f32.bf16.bf16.f32 "
        "{%0,%1,%2,%3}, {%4,%5,%6,%7}, {%8,%9}, {%0,%1,%2,%3};"
        : "+f"(c[0]), "+f"(c[1]), "+f"(c[2]), "+f"(c[3])
        : "r"(a[0]), "r"(a[1]), "r"(a[2]), "r"(a[3]), "r"(b0), "r"(b1));
}

// ---------------- kernel 0: init --------------------------------------------
__global__ void init_kernel(float* __restrict__ out) {
    int i = blockIdx.x * blockDim.x + threadIdx.x;
    if (i < NEXP) d_cnt[i] = 0;
    const int n4 = (T_TOK * HDIM) / 4;
    float4 z = make_float4(0.f, 0.f, 0.f, 0.f);
    float4* o4 = (float4*)out;
    for (int j = i; j < n4; j += gridDim.x * blockDim.x) o4[j] = z;
}

// ---------------- kernel 1: split x into bf16 hi/lo --------------------------
__global__ void convert_x(const float* __restrict__ x) {
    int n = (T_TOK * HDIM) / 4;
    const float4* x4 = (const float4*)x;
    for (int i = blockIdx.x * blockDim.x + threadIdx.x; i < n; i += gridDim.x * blockDim.x) {
        float4 v = x4[i];
        __nv_bfloat16 h0 = __float2bfloat16_rn(v.x), h1 = __float2bfloat16_rn(v.y);
        __nv_bfloat16 h2 = __float2bfloat16_rn(v.z), h3 = __float2bfloat16_rn(v.w);
        __nv_bfloat16 l0 = __float2bfloat16_rn(v.x - __bfloat162float(h0));
        __nv_bfloat16 l1 = __float2bfloat16_rn(v.y - __bfloat162float(h1));
        __nv_bfloat16 l2 = __float2bfloat16_rn(v.z - __bfloat162float(h2));
        __nv_bfloat16 l3 = __float2bfloat16_rn(v.w - __bfloat162float(h3));
        __nv_bfloat162 hv0 = {h0, h1}, hv1 = {h2, h3}, lv0 = {l0, l1}, lv1 = {l2, l3};
        ((__nv_bfloat162*)d_xhi)[2 * i]     = hv0;
        ((__nv_bfloat162*)d_xhi)[2 * i + 1] = hv1;
        ((__nv_bfloat162*)d_xlo)[2 * i]     = lv0;
        ((__nv_bfloat162*)d_xlo)[2 * i + 1] = lv1;
    }
}

// ---------------- kernel 2: transpose + split We -----------------------------
__global__ void transpose_we(const float* __restrict__ We) {
    __shared__ float tile[32][33];
    int e = blockIdx.z;
    int n0 = blockIdx.x * 32, k0 = blockIdx.y * 32;
    int tx = threadIdx.x & 31, ty = threadIdx.x >> 5;   // 32 x 8
    const float* src = We + ((size_t)e * HDIM + k0) * HDIM + n0;
#pragma unroll
    for (int i = 0; i < 4; i++)
        tile[ty + 8 * i][tx] = src[(size_t)(ty + 8 * i) * HDIM + tx];
    __syncthreads();
    size_t ob = ((size_t)e * HDIM + n0) * HDIM + k0;
#pragma unroll
    for (int i = 0; i < 4; i++) {
        float v = tile[tx][ty + 8 * i];
        __nv_bfloat16 h = __float2bfloat16_rn(v);
        __nv_bfloat16 l = __float2bfloat16_rn(v - __bfloat162float(h));
        d_wthi[ob + (size_t)(ty + 8 * i) * HDIM + tx] = h;
        d_wtlo[ob + (size_t)(ty + 8 * i) * HDIM + tx] = l;
    }
}

// ---------------- kernel 3: router (warp per token) --------------------------
__global__ void router_kernel(const float* __restrict__ x,
                              const float* __restrict__ Wg,
                              const float* __restrict__ bg) {
    const int wid_g = (blockIdx.x * blockDim.x + threadIdx.x) >> 5;   // global warp
    if (wid_g >= T_TOK) return;
    const int lane = threadIdx.x & 31;
    const int t = wid_g;

    float acc[NEXP];
#pragma unroll
    for (int e = 0; e < NEXP; e++) acc[e] = 0.f;

    const float4* xr = (const float4*)(x + (size_t)t * HDIM);
    // lane handles float4 indices lane, lane+32, ... (64 iterations over 512 f4)
#pragma unroll 4
    for (int j = 0; j < HDIM / 4 / 32; j++) {
        const int i4 = lane + j * 32;
        float4 xv = xr[i4];
        const int h = i4 * 4;
        // Wg rows h..h+3 are 4*8 = 32 contiguous floats
        const float4* wr = (const float4*)(Wg + (size_t)h * NEXP);
        float4 w0 = wr[0], w1 = wr[1], w2 = wr[2], w3 = wr[3];
        float4 w4 = wr[4], w5 = wr[5], w6 = wr[6], w7 = wr[7];
        acc[0] += xv.x * w0.x; acc[1] += xv.x * w0.y; acc[2] += xv.x * w0.z; acc[3] += xv.x * w0.w;
        acc[4] += xv.x * w1.x; acc[5] += xv.x * w1.y; acc[6] += xv.x * w1.z; acc[7] += xv.x * w1.w;
        acc[0] += xv.y * w2.x; acc[1] += xv.y * w2.y; acc[2] += xv.y * w2.z; acc[3] += xv.y * w2.w;
        acc[4] += xv.y * w3.x; acc[5] += xv.y * w3.y; acc[6] += xv.y * w3.z; acc[7] += xv.y * w3.w;
        acc[0] += xv.z * w4.x; acc[1] += xv.z * w4.y; acc[2] += xv.z * w4.z; acc[3] += xv.z * w4.w;
        acc[4] += xv.z * w5.x; acc[5] += xv.z * w5.y; acc[6] += xv.z * w5.z; acc[7] += xv.z * w5.w;
        acc[0] += xv.w * w6.x; acc[1] += xv.w * w6.y; acc[2] += xv.w * w6.z; acc[3] += xv.w * w6.w;
        acc[4] += xv.w * w7.x; acc[5] += xv.w * w7.y; acc[6] += xv.w * w7.z; acc[7] += xv.w * w7.w;
    }

    // butterfly reduce each logit across the warp
#pragma unroll
    for (int e = 0; e < NEXP; e++) {
#pragma unroll
        for (int s = 16; s > 0; s >>= 1)
            acc[e] += __shfl_xor_sync(0xFFFFFFFFu, acc[e], s);
    }

    if (lane == 0) {
#pragma unroll
        for (int e = 0; e < NEXP; e++) acc[e] += bg[e];
        float m = acc[0];
#pragma unroll
        for (int e = 1; e < NEXP; e++) m = fmaxf(m, acc[e]);
        float p[NEXP], s = 0.f;
#pragma unroll
        for (int e = 0; e < NEXP; e++) { p[e] = __expf(acc[e] - m); s += p[e]; }
        float inv = 1.f / s;
#pragma unroll
        for (int e = 0; e < NEXP; e++) p[e] *= inv;
        int i0 = 0;
#pragma unroll
        for (int e = 1; e < NEXP; e++) if (p[e] > p[i0]) i0 = e;
        int i1 = (i0 == 0) ? 1 : 0;
#pragma unroll
        for (int e = 0; e < NEXP; e++) if (e != i0 && p[e] > p[i1]) i1 = e;
        int pos0 = atomicAdd(&d_cnt[i0], 1);
        d_list[i0 * T_TOK + pos0] = t;  d_gatev[i0 * T_TOK + pos0] = p[i0];
        int pos1 = atomicAdd(&d_cnt[i1], 1);
        d_list[i1 * T_TOK + pos1] = t;  d_gatev[i1 * T_TOK + pos1] = p[i1];
    }
}

// ---------------- kernel 4: grouped GEMM via mma.sync bf16 -------------------
__global__ void __launch_bounds__(256, 1)
moe_gemm_mma(const float* __restrict__ be, float* __restrict__ out) {
    const int e = blockIdx.z;
    const int cnt = d_cnt[e];
    const int m0 = blockIdx.y * BM;
    if (m0 >= cnt) return;
    const int n0 = blockIdx.x * BN;

    extern __shared__ char smem[];
    const uint32_t sb = smem_u32(smem);
    const int tid  = threadIdx.x;
    const int wid  = tid >> 5;
    const int lane = tid & 31;
    const int wm   = wid >> 2;       // 0..1  (m: 64 each)
    const int wn   = wid & 3;        // 0..3  (n: 32 each)

    int*   sTok  = (int*)smem;
    float* sGate = (float*)(smem + 512);

    if (tid < BM) {
        int r = m0 + tid;
        if (r < cnt) { sTok[tid] = d_list[e * T_TOK + r]; sGate[tid] = d_gatev[e * T_TOK + r]; }
        else         { sTok[tid] = 0;                      sGate[tid] = 0.f; }
    }
    __syncthreads();

    // --- gmem gather sources (per thread; constant across chunks) ---
    const int row2 = tid >> 1;           // 0..127
    const int half = tid & 1;            // 64B half of the 128B row
    uint32_t sD[4];
#pragma unroll
    for (int i = 0; i < 4; i++) {
        uint32_t o = row2 * 128 + (half * 4 + i) * 16;
        sD[i] = o ^ ((o >> 3) & 0x70);   // SW128
    }
    const __nv_bfloat16* aHiS = d_xhi + (size_t)sTok[row2] * HDIM + half * 32;
    const __nv_bfloat16* aLoS = d_xlo + (size_t)sTok[row2] * HDIM + half * 32;
    const __nv_bfloat16* bHiS = d_wthi + ((size_t)e * HDIM + n0 + row2) * HDIM + half * 32;
    const __nv_bfloat16* bLoS = d_wtlo + ((size_t)e * HDIM + n0 + row2) * HDIM + half * 32;

#define ISSUE_CHUNK(stage, k0)                                            \
    {                                                                     \
        _Pragma("unroll")                                                 \
        for (int i = 0; i < 4; i++) {                                     \
            cp16((stage) + A_HI_OFF + sD[i], aHiS + (k0) + i * 8);        \
            cp16((stage) + A_LO_OFF + sD[i], aLoS + (k0) + i * 8);        \
            cp16((stage) + B_HI_OFF + sD[i], bHiS + (k0) + i * 8);        \
            cp16((stage) + B_LO_OFF + sD[i], bLoS + (k0) + i * 8);        \
        }                                                                 \
        asm volatile("cp.async.commit_group;" ::: "memory");              \
    }

    // --- ldmatrix addressing (per lane) ---
    uint32_t aRow[4], bRow[2];
#pragma unroll
    for (int mi = 0; mi < 4; mi++) aRow[mi] = wm * 64 + mi * 16 + (lane & 15);
#pragma unroll
    for (int j = 0; j < 2; j++)    bRow[j]  = wn * 32 + j * 16 + (lane & 15);
    const uint32_t kcHalf = (lane >> 4);   // 0 or 1: which 16B chunk of the k16

    float acc[4][4][4];
#pragma unroll
    for (int mi = 0; mi < 4; mi++)
#pragma unroll
        for (int nj = 0; nj < 4; nj++)
#pragma unroll
            for (int q = 0; q < 4; q++) acc[mi][nj][q] = 0.f;

    const uint32_t stgBase = sb + SM_HDR;

    // prologue: fill 3 stages
    ISSUE_CHUNK(stgBase + 0 * STAGE_BYTES, 0);
    ISSUE_CHUNK(stgBase + 1 * STAGE_BYTES, BKC);
    ISSUE_CHUNK(stgBase + 2 * STAGE_BYTES, 2 * BKC);

    int sidx = 0;
    for (int c = 0; c < NCHUNK; c++) {
        asm volatile("cp.async.wait_group 2;" ::: "memory");
        __syncthreads();
        const uint32_t stage = stgBase + sidx * STAGE_BYTES;

#pragma unroll
        for (int ks = 0; ks < 4; ks++) {
            const uint32_t kc = ks * 2 + kcHalf;
            uint32_t ah[4][4], al[4][4];
#pragma unroll
            for (int mi = 0; mi < 4; mi++) {
                uint32_t off = aRow[mi] * 128 + ((kc ^ (aRow[mi] & 7)) << 4);
                ldm4(stage + A_HI_OFF + off, ah[mi][0], ah[mi][1], ah[mi][2], ah[mi][3]);
                ldm4(stage + A_LO_OFF + off, al[mi][0], al[mi][1], al[mi][2], al[mi][3]);
            }
            uint32_t bh[2][4], bl[2][4];
#pragma unroll
            for (int j = 0; j < 2; j++) {
                uint32_t off = bRow[j] * 128 + ((kc ^ (bRow[j] & 7)) << 4);
                ldm4(stage + B_HI_OFF + off, bh[j][0], bh[j][1], bh[j][2], bh[j][3]);
                ldm4(stage + B_LO_OFF + off, bl[j][0], bl[j][1], bl[j][2], bl[j][3]);
            }
#pragma unroll
            for (int mi = 0; mi < 4; mi++) {
#pragma unroll
                for (int nj = 0; nj < 4; nj++) {
                    const int j = nj >> 1, h = nj & 1;
                    mma16816(acc[mi][nj], ah[mi], bh[j][h], bh[j][h + 2]);  // hi*hi
                    mma16816(acc[mi][nj], ah[mi], bl[j][h], bl[j][h + 2]);  // hi*lo
                    mma16816(acc[mi][nj], al[mi], bh[j][h], bh[j][h + 2]);  // lo*hi
                }
            }
        }

        __syncthreads();
        if (c + NSTAGE < NCHUNK) {
            ISSUE_CHUNK(stage, (c + NSTAGE) * BKC);
        } else {
            asm volatile("cp.async.commit_group;" ::: "memory");
        }
        sidx = (sidx == NSTAGE - 1) ? 0 : sidx + 1;
    }

    // --- epilogue: out[tok] += gate * (acc + be[e]) ---
    const float* beg = be + (size_t)e * HDIM + n0;
    const int cl = (lane & 3) * 2;
    const int rl = lane >> 2;
#pragma unroll
    for (int mi = 0; mi < 4; mi++) {
        const int r0 = wm * 64 + mi * 16 + rl;
        const int r1 = r0 + 8;
        const bool v0 = (m0 + r0) < cnt;
        const bool v1 = (m0 + r1) < cnt;
        const int   t0 = sTok[r0], t1 = sTok[r1];
        const float g0 = sGate[r0], g1 = sGate[r1];
        float* o0 = out + (size_t)t0 * HDIM + n0;
        float* o1 = out + (size_t)t1 * HDIM + n0;
#pragma unroll
        for (int nj = 0; nj < 4; nj++) {
            const int col = wn * 32 + nj * 8 + cl;
            const float b0 = beg[col], b1 = beg[col + 1];
            if (v0) {
                atomicAdd(&o0[col],     g0 * (acc[mi][nj][0] + b0));
                atomicAdd(&o0[col + 1], g0 * (acc[mi][nj][1] + b1));
            }
            if (v1) {
                atomicAdd(&o1[col],     g1 * (acc[mi][nj][2] + b0));
                atomicAdd(&o1[col + 1], g1 * (acc[mi][nj][3] + b1));
            }
        }
    }
}

// ---------------------------------------------------------------------------
extern "C" void kernel_launch(void* const* d_in, const int* in_sizes, int n_in,
                              void* d_out, int out_size) {
    const float* x  = (const float*)d_in[0];
    const float* Wg = (const float*)d_in[1];
    const float* bg = (const float*)d_in[2];
    const float* We = (const float*)d_in[3];
    const float* be = (const float*)d_in[4];
    float* out = (float*)d_out;

    cudaFuncSetAttribute(moe_gemm_mma, cudaFuncAttributeMaxDynamicSharedMemorySize, SMEM_TOTAL);

    init_kernel<<<1024, 256>>>(out);
    convert_x<<<2048, 256>>>(x);
    dim3 tg(HDIM / 32, HDIM / 32, NEXP);
    transpose_we<<<tg, 256>>>(We);
    router_kernel<<<T_TOK / 8, 256>>>(x, Wg, bg);   // 8 warps/block, warp per token

    dim3 grid(HDIM / BN, T_TOK / BM, NEXP);
    moe_gemm_mma<<<grid, 256, SMEM_TOTAL>>>(be, out);
}